// round 14
// baseline (speedup 1.0000x reference)
#include <cuda_runtime.h>
#include <cuda_bf16.h>
#include <cstdint>

// SpectralConv1d: forward = pruned cas-FFT butterfly (R12, proven),
// mix = cp.async double-buffered (R12, proven),
// inverse = mma.sync bf16-split GEMM (base-target ISA; tcgen05 is
//   unavailable: harness PTX target is compute_103 without 'a').
// out(8192x4096) = Z(8192x64) * G(4096x64)^T, 3-term bf16 split.

#define NN     4096
#define MODES  64
#define CH     128
#define ROWS   8192

#define SQ2   1.41421356237309515f
#define C256  1.30656296487637653f   // cas(pi/8)
#define C1280 0.54119610014619698f   // cas(5pi/8)

__device__ float g_CAS[2048];             // cas(2*pi*j/4096)
__device__ float g_OM[2048];              // omega[k<64][q<32]
__device__ float g_Y[MODES * ROWS];       // [m][row]
__device__ float g_Z[MODES * ROWS];       // [m][row]  (already /4096)
__device__ float g_We[MODES * CH * CH];   // [m][i][o]
__device__ float g_Wo[MODES * CH * CH];   // [m][i][o]

// bf16-split operands for the inverse GEMM
__device__ __align__(16) unsigned short g_Zhi[ROWS * 64];   // [row][k]
__device__ __align__(16) unsigned short g_Zlo[ROWS * 64];
__device__ __align__(16) unsigned short g_Ghi[NN * 64];     // [j][k]
__device__ __align__(16) unsigned short g_Glo[NN * 64];

__device__ __forceinline__ void cp16(uint32_t daddr, const void* gptr) {
    asm volatile("cp.async.cg.shared.global [%0], [%1], 16;" :: "r"(daddr), "l"(gptr));
}
__device__ __forceinline__ void cp_commit() {
    asm volatile("cp.async.commit_group;" ::: "memory");
}
__device__ __forceinline__ uint32_t smem_u32(const void* p) {
    uint32_t a;
    asm("{ .reg .u64 t; cvta.to.shared.u64 t, %1; cvt.u32.u64 %0, t; }" : "=r"(a) : "l"(p));
    return a;
}

#define LDSM4(r0, r1, r2, r3, addr) \
    asm volatile("ldmatrix.sync.aligned.m8n8.x4.shared.b16 {%0,%1,%2,%3}, [%4];" \
                 : "=r"(r0), "=r"(r1), "=r"(r2), "=r"(r3) : "r"(addr))

#define MMA16816(d, a0, a1, a2, a3, b0, b1) \
    asm volatile("mma.sync.aligned.m16n8k16.row.col.f32.bf16.bf16.f32 " \
                 "{%0,%1,%2,%3}, {%4,%5,%6,%7}, {%8,%9}, {%0,%1,%2,%3};" \
                 : "+f"((d)[0]), "+f"((d)[1]), "+f"((d)[2]), "+f"((d)[3]) \
                 : "r"(a0), "r"(a1), "r"(a2), "r"(a3), "r"(b0), "r"(b1))

// ---------------- tables ----------------
__global__ void build_tables_kernel() {
    int j = blockIdx.x * blockDim.x + threadIdx.x;
    if (j < 2048) {
        float s, c;
        sincospif((float)j * (1.0f / 2048.0f), &s, &c);
        g_CAS[j] = c + s;
    } else if (j < 4096) {
        int idx = j - 2048;
        int k = idx >> 5, q = idx & 31;
        float w = 1.0f;
        #pragma unroll
        for (int t = 0; t < 5; t++) {
            if ((q >> t) & 1) {
                float s, c;
                sincospif((float)(k << t) * (1.0f / 2048.0f), &s, &c);
                w *= (c + s);
            }
        }
        g_OM[idx] = w;
    }
}

__global__ __launch_bounds__(256) void build_wewo_kernel(const float* __restrict__ w1) {
    __shared__ float tile[64 * 129];
    int i = blockIdx.x, tid = threadIdx.x;
    const float* src = w1 + (size_t)i * 8192;
    for (int idx = tid; idx < 8192; idx += 256) {
        int o = idx >> 6, m = idx & 63;
        tile[m * 129 + o] = src[idx];
    }
    __syncthreads();
    for (int j = tid; j < 8192; j += 256) {
        int m = j >> 7, o = j & 127;
        int mn = (MODES - m) & 63;
        float a = tile[m * 129 + o];
        float b = tile[mn * 129 + o];
        size_t d = (size_t)m * 16384 + (size_t)i * 128 + o;
        g_We[d] = 0.5f * (a + b);
        g_Wo[d] = 0.5f * (a - b);
    }
}

__device__ __forceinline__ int brev4(int r) {
    return ((r & 1) << 3) | ((r & 2) << 1) | ((r & 4) >> 1) | ((r & 8) >> 3);
}

// ---------------- build G: inverse butterfly of basis vectors ----------------
__global__ __launch_bounds__(256) void build_G_kernel() {
    __shared__ float buf[4096];
    __shared__ float cas_s[2048];
    int h = threadIdx.x, k = blockIdx.x;

    for (int j = h; j < 2048; j += 256) cas_s[j] = g_CAS[j];
    __syncthreads();

    float v[16];
    #pragma unroll
    for (int r = 0; r < 16; r++)
        v[r] = (((h & 7) + ((r & 7) << 3)) == k) ? 1.0f : 0.0f;

    int hk = (h >> 3) & 31;
    #pragma unroll
    for (int r = 0; r < 16; r++) if (!(r & 4)) {
        float w = cas_s[(hk + ((r & 8) << 2)) << 5];
        float a = v[r], b = v[r + 4];
        v[r] = fmaf(w, b, a); v[r + 4] = fmaf(-w, b, a);
    }
    #pragma unroll
    for (int r = 0; r < 16; r++) if (!(r & 2)) {
        float w = cas_s[(hk + ((r & 8) << 2) + ((r & 4) << 4)) << 4];
        float a = v[r], b = v[r + 2];
        v[r] = fmaf(w, b, a); v[r + 2] = fmaf(-w, b, a);
    }
    #pragma unroll
    for (int r = 0; r < 16; r += 2) {
        float w = cas_s[(hk + ((r & 8) << 2) + ((r & 4) << 4) + ((r & 2) << 6)) << 3];
        float a = v[r], b = v[r + 1];
        v[r] = fmaf(w, b, a); v[r + 1] = fmaf(-w, b, a);
    }

    #pragma unroll
    for (int r = 0; r < 16; r++) {
        int a = h + (brev4(r) << 8);
        buf[a ^ ((a >> 5) & 7)] = v[r];
    }
    __syncthreads();
    #pragma unroll
    for (int r = 0; r < 16; r++) {
        int a = (r & 7) + (h << 3) + ((r & 8) << 8);
        v[r] = buf[a ^ ((a >> 5) & 7)];
    }

    #pragma unroll
    for (int r = 0; r < 16; r++) if (!(r & 4)) {
        float w = cas_s[(h + ((r & 8) << 5)) << 2];
        float a = v[r], b = v[r + 4];
        v[r] = fmaf(w, b, a); v[r + 4] = fmaf(-w, b, a);
    }
    #pragma unroll
    for (int r = 0; r < 16; r++) if (!(r & 2)) {
        float w = cas_s[(h + ((r & 8) << 5) + ((r & 4) << 7)) << 1];
        float a = v[r], b = v[r + 2];
        v[r] = fmaf(w, b, a); v[r + 2] = fmaf(-w, b, a);
    }
    #pragma unroll
    for (int r = 0; r < 16; r += 2) {
        float w = cas_s[h + ((r & 8) << 5) + ((r & 4) << 7) + ((r & 2) << 9)];
        float a = v[r], b = v[r + 1];
        v[r] = fmaf(w, b, a); v[r + 1] = fmaf(-w, b, a);
    }

    #pragma unroll
    for (int r = 0; r < 16; r++) {
        int j = h + (brev4(r) << 8);
        float gv = v[r];
        __nv_bfloat16 hb = __float2bfloat16_rn(gv);
        float rem = gv - __bfloat162float(hb);
        g_Ghi[(size_t)j * 64 + k] = __bfloat16_as_ushort(hb);
        g_Glo[(size_t)j * 64 + k] = __bfloat16_as_ushort(__float2bfloat16_rn(rem));
    }
}

// ---------------- forward (R12, unchanged) ----------------
__global__ __launch_bounds__(256, 6) void forward_kernel(const float* __restrict__ x) {
    __shared__ float buf[4096];
    __shared__ float cas32s[64];
    int h = threadIdx.x, row = blockIdx.x;
    int lane = h & 31, wrp = h >> 5;

    if (h < 64) cas32s[h] = g_CAS[h << 5];

    const float* xr = x + (size_t)row * NN;
    float v[16];
    #pragma unroll
    for (int r = 0; r < 16; r++) v[r] = xr[h + (r << 8)];

    float om[8];
    #pragma unroll
    for (int c = 0; c < 8; c++) om[c] = g_OM[((wrp + (c << 3)) << 5) + lane];

    #pragma unroll
    for (int r = 0; r < 8; r++) { float a = v[r], b = v[r + 8]; v[r] = a + b; v[r + 8] = a - b; }
    #pragma unroll
    for (int r = 0; r < 16; r++) if (!(r & 4)) { float a = v[r], b = v[r + 4]; v[r] = a + b; v[r + 4] = a - b; }
    {
        const float TW9[4] = {1.f, SQ2, 1.f, 0.f};
        #pragma unroll
        for (int r = 0; r < 16; r++) if (!(r & 2)) {
            int kt = ((r >> 3) & 1) | (((r >> 2) & 1) << 1);
            float w = TW9[kt], a = v[r], b = v[r + 2];
            v[r] = fmaf(w, b, a); v[r + 2] = fmaf(-w, b, a);
        }
    }
    {
        const float TW8[8] = {1.f, C256, SQ2, C256, 1.f, C1280, 0.f, -C1280};
        #pragma unroll
        for (int r = 0; r < 16; r += 2) {
            int kt = ((r >> 3) & 1) | (((r >> 2) & 1) << 1) | (((r >> 1) & 1) << 2);
            float w = TW8[kt], a = v[r], b = v[r + 1];
            v[r] = fmaf(w, b, a); v[r + 1] = fmaf(-w, b, a);
        }
    }
    #pragma unroll
    for (int r = 0; r < 16; r++) buf[h + (brev4(r) << 8)] = v[r];
    __syncthreads();

    int hi3 = wrp;
    int base = (h & 31) + (hi3 << 8);
    float u[16];
    #pragma unroll
    for (int r = 0; r < 16; r++) u[r] = buf[base + ((r & 7) << 5) + ((r & 8) << 8)];
    #pragma unroll
    for (int r = 0; r < 16; r++) if (!(r & 4)) {
        float w = cas32s[(hi3 + (r & 8)) << 2];
        float a = u[r], b = u[r + 4];
        u[r] = fmaf(w, b, a); u[r + 4] = fmaf(-w, b, a);
    }
    #pragma unroll
    for (int r = 0; r < 16; r++) if (!(r & 2)) {
        float w = cas32s[(hi3 + (r & 8) + ((r & 4) << 2)) << 1];
        float a = u[r], b = u[r + 2];
        u[r] = fmaf(w, b, a); u[r + 2] = fmaf(-w, b, a);
    }
    #pragma unroll
    for (int r = 0; r < 16; r += 2) {
        float w = cas32s[hi3 + (r & 8) + ((r & 4) << 2) + ((r & 2) << 4)];
        u[r] = fmaf(w, u[r + 1], u[r]);
    }

    float val[8];
    #pragma unroll
    for (int c = 0; c < 8; c++) {
        int j = ((c & 1) << 2) | (c & 2) | ((c & 4) >> 2);
        val[c] = om[c] * u[2 * j];
    }
    bool b4 = (lane & 16) != 0, b3 = (lane & 8) != 0, b2 = (lane & 4) != 0;
    float a4[4];
    #pragma unroll
    for (int c = 0; c < 4; c++) {
        float keep = b4 ? val[c + 4] : val[c];
        float give = b4 ? val[c] : val[c + 4];
        a4[c] = keep + __shfl_xor_sync(0xffffffffu, give, 16);
    }
    float a2[2];
    #pragma unroll
    for (int c = 0; c < 2; c++) {
        float keep = b3 ? a4[c + 2] : a4[c];
        float give = b3 ? a4[c] : a4[c + 2];
        a2[c] = keep + __shfl_xor_sync(0xffffffffu, give, 8);
    }
    float e;
    {
        float keep = b2 ? a2[1] : a2[0];
        float give = b2 ? a2[0] : a2[1];
        e = keep + __shfl_xor_sync(0xffffffffu, give, 4);
    }
    e += __shfl_xor_sync(0xffffffffu, e, 2);
    e += __shfl_xor_sync(0xffffffffu, e, 1);
    if ((lane & 3) == 0) g_Y[(wrp + ((lane >> 2) << 3)) * ROWS + row] = e;
}

// ---------------- mix (R12, unchanged) ----------------
__global__ __launch_bounds__(128) void mix_kernel() {
    __shared__ float Ys[8 * CH];
    __shared__ float Yn[8 * CH];
    extern __shared__ float4 Wbuf[];

    int m = blockIdx.x >> 3, g = blockIdx.x & 7;
    int mn = (MODES - m) & 63;
    int tid = threadIdx.x;
    int oq = tid & 31, bg = tid >> 5;

    const float* We = g_We + (size_t)m * 16384;
    const float* Wo = g_Wo + (size_t)m * 16384;
    uint32_t wb = (uint32_t)__cvta_generic_to_shared(Wbuf);

    #define ISSUE_CHUNK(c, s) do {                                              \
        const float4* se = (const float4*)(We + (c) * 2048);                    \
        const float4* so = (const float4*)(Wo + (c) * 2048);                    \
        uint32_t de = wb + (uint32_t)((s) * 2 + 0) * 8192;                      \
        uint32_t dn = wb + (uint32_t)((s) * 2 + 1) * 8192;                      \
        _Pragma("unroll")                                                       \
        for (int jj = 0; jj < 4; jj++) {                                        \
            int idx = tid + jj * 128;                                           \
            cp16(de + idx * 16, se + idx);                                      \
            cp16(dn + idx * 16, so + idx);                                      \
        }                                                                       \
        cp_commit();                                                            \
    } while (0)

    ISSUE_CHUNK(0, 0);
    ISSUE_CHUNK(1, 1);

    for (int idx = tid; idx < 1024; idx += 128) {
        Ys[idx] = g_Y[m * ROWS + g * 1024 + idx];
        Yn[idx] = g_Y[mn * ROWS + g * 1024 + idx];
    }

    float4 a0 = {0,0,0,0}, a1 = {0,0,0,0};
    int l0 = 2 * bg, l1 = l0 + 1;

    #pragma unroll 1
    for (int c = 0; c < 8; c++) {
        if (c < 7) asm volatile("cp.async.wait_group 1;" ::: "memory");
        else       asm volatile("cp.async.wait_group 0;" ::: "memory");
        __syncthreads();

        const float4* Wef = &Wbuf[(size_t)((c & 1) * 2 + 0) * 512];
        const float4* Wof = &Wbuf[(size_t)((c & 1) * 2 + 1) * 512];
        #pragma unroll
        for (int ii = 0; ii < 16; ii++) {
            float4 we = Wef[ii * 32 + oq];
            float4 wo = Wof[ii * 32 + oq];
            int i = c * 16 + ii;
            float y0 = Ys[l0 * CH + i], z0 = Yn[l0 * CH + i];
            float y1 = Ys[l1 * CH + i], z1 = Yn[l1 * CH + i];
            a0.x = fmaf(y0, we.x, a0.x); a0.x = fmaf(z0, wo.x, a0.x);
            a0.y = fmaf(y0, we.y, a0.y); a0.y = fmaf(z0, wo.y, a0.y);
            a0.z = fmaf(y0, we.z, a0.z); a0.z = fmaf(z0, wo.z, a0.z);
            a0.w = fmaf(y0, we.w, a0.w); a0.w = fmaf(z0, wo.w, a0.w);
            a1.x = fmaf(y1, we.x, a1.x); a1.x = fmaf(z1, wo.x, a1.x);
            a1.y = fmaf(y1, we.y, a1.y); a1.y = fmaf(z1, wo.y, a1.y);
            a1.z = fmaf(y1, we.z, a1.z); a1.z = fmaf(z1, wo.z, a1.z);
            a1.w = fmaf(y1, we.w, a1.w); a1.w = fmaf(z1, wo.w, a1.w);
        }
        __syncthreads();
        if (c < 6) ISSUE_CHUNK(c + 2, c & 1);
    }

    const float inv = 1.0f / 4096.0f;
    float4* Z4 = (float4*)g_Z;
    float4 s0 = make_float4(a0.x * inv, a0.y * inv, a0.z * inv, a0.w * inv);
    float4 s1 = make_float4(a1.x * inv, a1.y * inv, a1.z * inv, a1.w * inv);
    int b0 = g * 8 + l0;
    Z4[(size_t)m * 2048 + (size_t)b0 * 32 + oq]       = s0;
    Z4[(size_t)m * 2048 + (size_t)(b0 + 1) * 32 + oq] = s1;
    #undef ISSUE_CHUNK
}

// ---------------- repack z: [m][row] fp32 -> [row][k] bf16 hi/lo ----------------
__global__ __launch_bounds__(256) void repack_z_kernel() {
    __shared__ float t[64 * 65];
    int base = blockIdx.x * 64, tid = threadIdx.x;
    for (int idx = tid; idx < 4096; idx += 256) {
        int m = idx >> 6, r = idx & 63;
        t[r * 65 + m] = g_Z[(size_t)m * 8192 + base + r];
    }
    __syncthreads();
    for (int idx = tid; idx < 4096; idx += 256) {
        int r = idx >> 6, k = idx & 63;
        float f = t[r * 65 + k];
        __nv_bfloat16 hb = __float2bfloat16_rn(f);
        float rem = f - __bfloat162float(hb);
        g_Zhi[(size_t)(base + r) * 64 + k] = __bfloat16_as_ushort(hb);
        g_Zlo[(size_t)(base + r) * 64 + k] = __bfloat16_as_ushort(__float2bfloat16_rn(rem));
    }
}

// ---------------- inverse GEMM via mma.sync ----------------
// CTA: 64(M) x 64(N) tile, 4 warps (warp = 16 rows x 64 cols), K=64.
// smem: A hi/lo 8KB each, B hi/lo 8KB each; rows 128B, XOR-16B swizzled.
#define SMA_HI 0
#define SMA_LO 8192
#define SMB_HI 16384
#define SMB_LO 24576

__global__ __launch_bounds__(128) void inv_mma_kernel(float* __restrict__ out) {
    __shared__ __align__(16) unsigned char smem[32768];
    uint32_t sb = smem_u32(smem);
    int tid = threadIdx.x, wm = tid >> 5, lane = tid & 31;
    int mt = blockIdx.x >> 6;   // 128 m-tiles
    int nt = blockIdx.x & 63;   // 64 n-tiles

    // load tiles: 64 rows x 8 16B-chunks each matrix
    const uint4* Ah = ((const uint4*)g_Zhi) + (size_t)mt * 512;
    const uint4* Al = ((const uint4*)g_Zlo) + (size_t)mt * 512;
    const uint4* Bh = ((const uint4*)g_Ghi) + (size_t)nt * 512;
    const uint4* Bl = ((const uint4*)g_Glo) + (size_t)nt * 512;
    #pragma unroll
    for (int j = 0; j < 4; j++) {
        int idx = tid + j * 128;
        int r = idx >> 3, c = idx & 7;
        uint32_t d = (uint32_t)(r * 128 + ((c * 16) ^ ((r & 7) << 4)));
        cp16(sb + SMA_HI + d, Ah + idx);
        cp16(sb + SMA_LO + d, Al + idx);
        cp16(sb + SMB_HI + d, Bh + idx);
        cp16(sb + SMB_LO + d, Bl + idx);
    }
    cp_commit();
    asm volatile("cp.async.wait_group 0;" ::: "memory");
    __syncthreads();

    float acc[32];
    #pragma unroll
    for (int i = 0; i < 32; i++) acc[i] = 0.0f;

    int l7 = lane & 7, lb3 = (lane >> 3) & 1, lb4 = lane >> 4;
    uint32_t a_row = (uint32_t)(wm * 16 + l7 + lb3 * 8);

    #pragma unroll
    for (int ks = 0; ks < 4; ks++) {
        uint32_t kbA = (uint32_t)(ks * 32 + lb4 * 16);
        uint32_t a_off = a_row * 128 + (kbA ^ ((a_row & 7) << 4));
        uint32_t ah0, ah1, ah2, ah3, al0, al1, al2, al3;
        LDSM4(ah0, ah1, ah2, ah3, sb + SMA_HI + a_off);
        LDSM4(al0, al1, al2, al3, sb + SMA_LO + a_off);

        uint32_t kbB = (uint32_t)(ks * 32 + lb3 * 16);
        uint32_t bh[16];
        #pragma unroll
        for (int j2 = 0; j2 < 4; j2++) {
            uint32_t n = (uint32_t)((2 * j2 + lb4) * 8 + l7);
            uint32_t b_off = n * 128 + (kbB ^ ((n & 7) << 4));
            LDSM4(bh[4 * j2], bh[4 * j2 + 1], bh[4 * j2 + 2], bh[4 * j2 + 3],
                  sb + SMB_HI + b_off);
        }
        #pragma unroll
        for (int g = 0; g < 8; g++)
            MMA16816(acc + g * 4, ah0, ah1, ah2, ah3, bh[2 * g], bh[2 * g + 1]);
        #pragma unroll
        for (int g = 0; g < 8; g++)
            MMA16816(acc + g * 4, al0, al1, al2, al3, bh[2 * g], bh[2 * g + 1]);
        #pragma unroll
        for (int j2 = 0; j2 < 4; j2++) {
            uint32_t n = (uint32_t)((2 * j2 + lb4) * 8 + l7);
            uint32_t b_off = n * 128 + (kbB ^ ((n & 7) << 4));
            uint32_t bl0, bl1, bl2, bl3;
            LDSM4(bl0, bl1, bl2, bl3, sb + SMB_LO + b_off);
            MMA16816(acc + (2 * j2) * 4,     ah0, ah1, ah2, ah3, bl0, bl1);
            MMA16816(acc + (2 * j2 + 1) * 4, ah0, ah1, ah2, ah3, bl2, bl3);
        }
    }

    // epilogue: c0,c1 -> (row g, cols 2tig..), c2,c3 -> (row g+8)
    int g = lane >> 2, tig = lane & 3;
    float2* out2 = (float2*)out;
    size_t row_lo = (size_t)(mt * 64 + wm * 16 + g);
    size_t row_hi = row_lo + 8;
    int colh = nt * 32;
    #pragma unroll
    for (int jb = 0; jb < 8; jb++) {
        float2 v0; v0.x = acc[jb * 4 + 0]; v0.y = acc[jb * 4 + 1];
        float2 v1; v1.x = acc[jb * 4 + 2]; v1.y = acc[jb * 4 + 3];
        out2[row_lo * 2048 + colh + jb * 4 + tig] = v0;
        out2[row_hi * 2048 + colh + jb * 4 + tig] = v1;
    }
}

extern "C" void kernel_launch(void* const* d_in, const int* in_sizes, int n_in,
                              void* d_out, int out_size) {
    const float* x  = (const float*)d_in[0];
    const float* w1 = (const float*)d_in[1];
    float* out = (float*)d_out;

    build_tables_kernel<<<16, 256>>>();
    build_wewo_kernel<<<CH, 256>>>(w1);
    build_G_kernel<<<64, 256>>>();
    forward_kernel<<<ROWS, 256>>>(x);
    mix_kernel<<<MODES * 8, 128, 32768>>>();
    repack_z_kernel<<<128, 256>>>();
    inv_mma_kernel<<<128 * 64, 128>>>(out);
}

// round 15
// speedup vs baseline: 1.1750x; 1.1750x over previous
#include <cuda_runtime.h>
#include <cstdint>

// SpectralConv1d via pruned cas-FFT (R12 pipeline; tensor path abandoned —
// harness targets compute_103, tcgen05 unavailable, legacy mma.sync slow).
// R15 delta: inverse twiddles from per-level UNIT-STRIDE tables (kills the
// 2/4-way smem bank conflicts of strided cas_s[kt<<t] lookups), and the
// inverse processes 2 rows per block to amortize the 16KB table load.

#define NN     4096
#define MODES  64
#define CH     128
#define ROWS   8192

#define SQ2   1.41421356237309515f
#define C256  1.30656296487637653f   // cas(pi/8)
#define C1280 0.54119610014619698f   // cas(5pi/8)

__device__ float g_CAS[2048];             // cas(2*pi*j/4096)
__device__ float g_CASP[4096];            // packed per-level tables (t=0..5)
__device__ float g_OM[2048];              // omega[k<64][q<32]
__device__ float g_Y[MODES * ROWS];       // [m][row]
__device__ float g_Z[MODES * ROWS];       // [m][row]  (already /4096)
__device__ float g_We[MODES * CH * CH];   // [m][i][o]
__device__ float g_Wo[MODES * CH * CH];   // [m][i][o]

// packed table offsets: [t0:2048][t1:1024][t2:512][t3:256][t4:128][t5:64]
#define OT1 2048
#define OT2 3072
#define OT3 3584
#define OT4 3840
#define OT5 3968

__global__ void build_tables_kernel() {
    int j = blockIdx.x * blockDim.x + threadIdx.x;
    if (j < 2048) {
        float s, c;
        sincospif((float)j * (1.0f / 2048.0f), &s, &c);
        g_CAS[j] = c + s;
    } else if (j < 4096) {
        int idx = j - 2048;
        int k = idx >> 5, q = idx & 31;
        float w = 1.0f;
        #pragma unroll
        for (int t = 0; t < 5; t++) {
            if ((q >> t) & 1) {
                float s, c;
                sincospif((float)(k << t) * (1.0f / 2048.0f), &s, &c);
                w *= (c + s);
            }
        }
        g_OM[idx] = w;
    } else if (j < 8192) {
        int p = j - 4096;
        int t, kt;
        if      (p < 2048) { t = 0; kt = p; }
        else if (p < 3072) { t = 1; kt = p - 2048; }
        else if (p < 3584) { t = 2; kt = p - 3072; }
        else if (p < 3840) { t = 3; kt = p - 3584; }
        else if (p < 3968) { t = 4; kt = p - 3840; }
        else if (p < 4032) { t = 5; kt = p - 3968; }
        else               { g_CASP[p] = 0.0f; return; }
        float s, c;
        sincospif((float)(kt << t) * (1.0f / 2048.0f), &s, &c);
        g_CASP[p] = c + s;
    }
}

// One block per i. Coalesced gmem read (m-fast), smem transpose (pad 129),
// coalesced gmem write (o-fast).
__global__ __launch_bounds__(256) void build_wewo_kernel(const float* __restrict__ w1) {
    __shared__ float tile[64 * 129];
    int i = blockIdx.x, tid = threadIdx.x;
    const float* src = w1 + (size_t)i * 8192;   // [o][m], m fast
    for (int idx = tid; idx < 8192; idx += 256) {
        int o = idx >> 6, m = idx & 63;
        tile[m * 129 + o] = src[idx];
    }
    __syncthreads();
    for (int j = tid; j < 8192; j += 256) {
        int m = j >> 7, o = j & 127;
        int mn = (MODES - m) & 63;
        float a = tile[m * 129 + o];
        float b = tile[mn * 129 + o];
        size_t d = (size_t)m * 16384 + (size_t)i * 128 + o;
        g_We[d] = 0.5f * (a + b);
        g_Wo[d] = 0.5f * (a - b);
    }
}

__device__ __forceinline__ int brev4(int r) {
    return ((r & 1) << 3) | ((r & 2) << 1) | ((r & 4) >> 1) | ((r & 8) >> 3);
}

// ---------------- forward (R12, unchanged) ----------------
__global__ __launch_bounds__(256, 6) void forward_kernel(const float* __restrict__ x) {
    __shared__ float buf[4096];
    __shared__ float cas32s[64];
    int h = threadIdx.x, row = blockIdx.x;
    int lane = h & 31, wrp = h >> 5;

    if (h < 64) cas32s[h] = g_CAS[h << 5];

    const float* xr = x + (size_t)row * NN;
    float v[16];
    #pragma unroll
    for (int r = 0; r < 16; r++) v[r] = xr[h + (r << 8)];

    float om[8];
    #pragma unroll
    for (int c = 0; c < 8; c++) om[c] = g_OM[((wrp + (c << 3)) << 5) + lane];

    #pragma unroll
    for (int r = 0; r < 8; r++) { float a = v[r], b = v[r + 8]; v[r] = a + b; v[r + 8] = a - b; }
    #pragma unroll
    for (int r = 0; r < 16; r++) if (!(r & 4)) { float a = v[r], b = v[r + 4]; v[r] = a + b; v[r + 4] = a - b; }
    {
        const float TW9[4] = {1.f, SQ2, 1.f, 0.f};
        #pragma unroll
        for (int r = 0; r < 16; r++) if (!(r & 2)) {
            int kt = ((r >> 3) & 1) | (((r >> 2) & 1) << 1);
            float w = TW9[kt], a = v[r], b = v[r + 2];
            v[r] = fmaf(w, b, a); v[r + 2] = fmaf(-w, b, a);
        }
    }
    {
        const float TW8[8] = {1.f, C256, SQ2, C256, 1.f, C1280, 0.f, -C1280};
        #pragma unroll
        for (int r = 0; r < 16; r += 2) {
            int kt = ((r >> 3) & 1) | (((r >> 2) & 1) << 1) | (((r >> 1) & 1) << 2);
            float w = TW8[kt], a = v[r], b = v[r + 1];
            v[r] = fmaf(w, b, a); v[r + 1] = fmaf(-w, b, a);
        }
    }
    #pragma unroll
    for (int r = 0; r < 16; r++) buf[h + (brev4(r) << 8)] = v[r];
    __syncthreads();

    int hi3 = wrp;
    int base = (h & 31) + (hi3 << 8);
    float u[16];
    #pragma unroll
    for (int r = 0; r < 16; r++) u[r] = buf[base + ((r & 7) << 5) + ((r & 8) << 8)];
    #pragma unroll
    for (int r = 0; r < 16; r++) if (!(r & 4)) {
        float w = cas32s[(hi3 + (r & 8)) << 2];
        float a = u[r], b = u[r + 4];
        u[r] = fmaf(w, b, a); u[r + 4] = fmaf(-w, b, a);
    }
    #pragma unroll
    for (int r = 0; r < 16; r++) if (!(r & 2)) {
        float w = cas32s[(hi3 + (r & 8) + ((r & 4) << 2)) << 1];
        float a = u[r], b = u[r + 2];
        u[r] = fmaf(w, b, a); u[r + 2] = fmaf(-w, b, a);
    }
    #pragma unroll
    for (int r = 0; r < 16; r += 2) {
        float w = cas32s[hi3 + (r & 8) + ((r & 4) << 2) + ((r & 2) << 4)];
        u[r] = fmaf(w, u[r + 1], u[r]);
    }

    float val[8];
    #pragma unroll
    for (int c = 0; c < 8; c++) {
        int j = ((c & 1) << 2) | (c & 2) | ((c & 4) >> 2);
        val[c] = om[c] * u[2 * j];
    }
    bool b4 = (lane & 16) != 0, b3 = (lane & 8) != 0, b2 = (lane & 4) != 0;
    float a4[4];
    #pragma unroll
    for (int c = 0; c < 4; c++) {
        float keep = b4 ? val[c + 4] : val[c];
        float give = b4 ? val[c] : val[c + 4];
        a4[c] = keep + __shfl_xor_sync(0xffffffffu, give, 16);
    }
    float a2[2];
    #pragma unroll
    for (int c = 0; c < 2; c++) {
        float keep = b3 ? a4[c + 2] : a4[c];
        float give = b3 ? a4[c] : a4[c + 2];
        a2[c] = keep + __shfl_xor_sync(0xffffffffu, give, 8);
    }
    float e;
    {
        float keep = b2 ? a2[1] : a2[0];
        float give = b2 ? a2[0] : a2[1];
        e = keep + __shfl_xor_sync(0xffffffffu, give, 4);
    }
    e += __shfl_xor_sync(0xffffffffu, e, 2);
    e += __shfl_xor_sync(0xffffffffu, e, 1);
    if ((lane & 3) == 0) g_Y[(wrp + ((lane >> 2) << 3)) * ROWS + row] = e;
}

// ---------------- mix (R12, unchanged) ----------------
__device__ __forceinline__ void cp16(uint32_t daddr, const void* gptr) {
    asm volatile("cp.async.cg.shared.global [%0], [%1], 16;" :: "r"(daddr), "l"(gptr));
}

__global__ __launch_bounds__(128) void mix_kernel() {
    __shared__ float Ys[8 * CH];
    __shared__ float Yn[8 * CH];
    extern __shared__ float4 Wbuf[];

    int m = blockIdx.x >> 3, g = blockIdx.x & 7;
    int mn = (MODES - m) & 63;
    int tid = threadIdx.x;
    int oq = tid & 31, bg = tid >> 5;

    const float* We = g_We + (size_t)m * 16384;
    const float* Wo = g_Wo + (size_t)m * 16384;
    uint32_t wb = (uint32_t)__cvta_generic_to_shared(Wbuf);

    #define ISSUE_CHUNK(c, s) do {                                              \
        const float4* se = (const float4*)(We + (c) * 2048);                    \
        const float4* so = (const float4*)(Wo + (c) * 2048);                    \
        uint32_t de = wb + (uint32_t)((s) * 2 + 0) * 8192;                      \
        uint32_t dn = wb + (uint32_t)((s) * 2 + 1) * 8192;                      \
        _Pragma("unroll")                                                       \
        for (int jj = 0; jj < 4; jj++) {                                        \
            int idx = tid + jj * 128;                                           \
            cp16(de + idx * 16, se + idx);                                      \
            cp16(dn + idx * 16, so + idx);                                      \
        }                                                                       \
        asm volatile("cp.async.commit_group;" ::: "memory");                    \
    } while (0)

    ISSUE_CHUNK(0, 0);
    ISSUE_CHUNK(1, 1);

    for (int idx = tid; idx < 1024; idx += 128) {
        Ys[idx] = g_Y[m * ROWS + g * 1024 + idx];
        Yn[idx] = g_Y[mn * ROWS + g * 1024 + idx];
    }

    float4 a0 = {0,0,0,0}, a1 = {0,0,0,0};
    int l0 = 2 * bg, l1 = l0 + 1;

    #pragma unroll 1
    for (int c = 0; c < 8; c++) {
        if (c < 7) asm volatile("cp.async.wait_group 1;" ::: "memory");
        else       asm volatile("cp.async.wait_group 0;" ::: "memory");
        __syncthreads();

        const float4* Wef = &Wbuf[(size_t)((c & 1) * 2 + 0) * 512];
        const float4* Wof = &Wbuf[(size_t)((c & 1) * 2 + 1) * 512];
        #pragma unroll
        for (int ii = 0; ii < 16; ii++) {
            float4 we = Wef[ii * 32 + oq];
            float4 wo = Wof[ii * 32 + oq];
            int i = c * 16 + ii;
            float y0 = Ys[l0 * CH + i], z0 = Yn[l0 * CH + i];
            float y1 = Ys[l1 * CH + i], z1 = Yn[l1 * CH + i];
            a0.x = fmaf(y0, we.x, a0.x); a0.x = fmaf(z0, wo.x, a0.x);
            a0.y = fmaf(y0, we.y, a0.y); a0.y = fmaf(z0, wo.y, a0.y);
            a0.z = fmaf(y0, we.z, a0.z); a0.z = fmaf(z0, wo.z, a0.z);
            a0.w = fmaf(y0, we.w, a0.w); a0.w = fmaf(z0, wo.w, a0.w);
            a1.x = fmaf(y1, we.x, a1.x); a1.x = fmaf(z1, wo.x, a1.x);
            a1.y = fmaf(y1, we.y, a1.y); a1.y = fmaf(z1, wo.y, a1.y);
            a1.z = fmaf(y1, we.z, a1.z); a1.z = fmaf(z1, wo.z, a1.z);
            a1.w = fmaf(y1, we.w, a1.w); a1.w = fmaf(z1, wo.w, a1.w);
        }
        __syncthreads();
        if (c < 6) ISSUE_CHUNK(c + 2, c & 1);
    }

    const float inv = 1.0f / 4096.0f;
    float4* Z4 = (float4*)g_Z;
    float4 s0 = make_float4(a0.x * inv, a0.y * inv, a0.z * inv, a0.w * inv);
    float4 s1 = make_float4(a1.x * inv, a1.y * inv, a1.z * inv, a1.w * inv);
    int b0 = g * 8 + l0;
    Z4[(size_t)m * 2048 + (size_t)b0 * 32 + oq]       = s0;
    Z4[(size_t)m * 2048 + (size_t)(b0 + 1) * 32 + oq] = s1;
    #undef ISSUE_CHUNK
}

// ---------------- inverse: packed unit-stride twiddles, 2 rows/block ----------------
__global__ __launch_bounds__(256, 6) void inverse_kernel(float* __restrict__ out) {
    __shared__ float buf[4096];
    __shared__ float casP[4096];
    __shared__ float zb[2][64];
    int h = threadIdx.x;
    int row0 = blockIdx.x * 2;

    {
        float4* c4 = (float4*)casP;
        const float4* s4 = (const float4*)g_CASP;
        #pragma unroll
        for (int j = 0; j < 4; j++) c4[h + (j << 8)] = s4[h + (j << 8)];
    }
    if (h < 128) zb[h >> 6][h & 63] = g_Z[(size_t)(h & 63) * ROWS + row0 + (h >> 6)];
    __syncthreads();

    int hk = (h >> 3) & 31;

    #pragma unroll
    for (int rr = 0; rr < 2; rr++) {
        const float* z = zb[rr];
        float v[16];
        #pragma unroll
        for (int r = 0; r < 16; r++) v[r] = z[(h & 7) + ((r & 7) << 3)];

        // t=5: kt = hk + 32*rb3
        #pragma unroll
        for (int r = 0; r < 16; r++) if (!(r & 4)) {
            float w = casP[OT5 + hk + ((r & 8) << 2)];
            float a = v[r], b = v[r + 4];
            v[r] = fmaf(w, b, a); v[r + 4] = fmaf(-w, b, a);
        }
        // t=4: kt = hk + 32*rb3 + 64*rb2
        #pragma unroll
        for (int r = 0; r < 16; r++) if (!(r & 2)) {
            float w = casP[OT4 + hk + ((r & 8) << 2) + ((r & 4) << 4)];
            float a = v[r], b = v[r + 2];
            v[r] = fmaf(w, b, a); v[r + 2] = fmaf(-w, b, a);
        }
        // t=3: kt = hk + 32*rb3 + 64*rb2 + 128*rb1
        #pragma unroll
        for (int r = 0; r < 16; r += 2) {
            float w = casP[OT3 + hk + ((r & 8) << 2) + ((r & 4) << 4) + ((r & 2) << 6)];
            float a = v[r], b = v[r + 1];
            v[r] = fmaf(w, b, a); v[r + 1] = fmaf(-w, b, a);
        }

        // exchange (swizzled, conflict-free both directions)
        #pragma unroll
        for (int r = 0; r < 16; r++) {
            int a = h + (brev4(r) << 8);
            buf[a ^ ((a >> 5) & 7)] = v[r];
        }
        __syncthreads();
        #pragma unroll
        for (int r = 0; r < 16; r++) {
            int a = (r & 7) + (h << 3) + ((r & 8) << 8);
            v[r] = buf[a ^ ((a >> 5) & 7)];
        }

        // t=2: kt = h + 256*rb3
        #pragma unroll
        for (int r = 0; r < 16; r++) if (!(r & 4)) {
            float w = casP[OT2 + h + ((r & 8) << 5)];
            float a = v[r], b = v[r + 4];
            v[r] = fmaf(w, b, a); v[r + 4] = fmaf(-w, b, a);
        }
        // t=1: kt = h + 256*rb3 + 512*rb2
        #pragma unroll
        for (int r = 0; r < 16; r++) if (!(r & 2)) {
            float w = casP[OT1 + h + ((r & 8) << 5) + ((r & 4) << 7)];
            float a = v[r], b = v[r + 2];
            v[r] = fmaf(w, b, a); v[r + 2] = fmaf(-w, b, a);
        }
        // t=0: kt = h + 256*rb3 + 512*rb2 + 1024*rb1
        #pragma unroll
        for (int r = 0; r < 16; r += 2) {
            float w = casP[h + ((r & 8) << 5) + ((r & 4) << 7) + ((r & 2) << 9)];
            float a = v[r], b = v[r + 1];
            v[r] = fmaf(w, b, a); v[r + 1] = fmaf(-w, b, a);
        }

        // direct coalesced stores
        float* orow = out + (size_t)(row0 + rr) * NN;
        #pragma unroll
        for (int r = 0; r < 16; r++) orow[h + (brev4(r) << 8)] = v[r];

        __syncthreads();   // buf reads done before next row's writes
    }
}

extern "C" void kernel_launch(void* const* d_in, const int* in_sizes, int n_in,
                              void* d_out, int out_size) {
    const float* x  = (const float*)d_in[0];
    const float* w1 = (const float*)d_in[1];
    float* out = (float*)d_out;

    build_tables_kernel<<<32, 256>>>();
    build_wewo_kernel<<<CH, 256>>>(w1);
    forward_kernel<<<ROWS, 256>>>(x);
    mix_kernel<<<MODES * 8, 128, 32768>>>();
    inverse_kernel<<<ROWS / 2, 256>>>(out);
}

// round 16
// speedup vs baseline: 1.3270x; 1.1294x over previous
#include <cuda_runtime.h>
#include <cstdint>

// SpectralConv1d via pruned cas-FFT (R12 pipeline, measured best).
// R16 delta: builds merged into ONE kernel (4 launches total -> inverse is
// launch index 3 and gets ncu-profiled), cas table loaded via float4,
// inverse output stores use streaming hint (__stcs).

#define NN     4096
#define MODES  64
#define CH     128
#define ROWS   8192

#define SQ2   1.41421356237309515f
#define C256  1.30656296487637653f   // cas(pi/8)
#define C1280 0.54119610014619698f   // cas(5pi/8)

__device__ __align__(16) float g_CAS[2048];   // cas(2*pi*j/4096)
__device__ __align__(16) float g_OM[2048];    // omega[k<64][q<32]
__device__ float g_Y[MODES * ROWS];           // [m][row]
__device__ float g_Z[MODES * ROWS];           // [m][row]  (already /4096)
__device__ float g_We[MODES * CH * CH];       // [m][i][o]
__device__ float g_Wo[MODES * CH * CH];       // [m][i][o]

// ---------------- merged build: blocks 0-127 = wewo, 128-159 = tables ----------------
__global__ __launch_bounds__(256) void build_all_kernel(const float* __restrict__ w1) {
    __shared__ float tile[64 * 129];
    int b = blockIdx.x, tid = threadIdx.x;

    if (b < 128) {
        // wewo transpose: coalesced read (m-fast), padded smem, coalesced write
        int i = b;
        const float* src = w1 + (size_t)i * 8192;   // [o][m], m fast
        for (int idx = tid; idx < 8192; idx += 256) {
            int o = idx >> 6, m = idx & 63;
            tile[m * 129 + o] = src[idx];
        }
        __syncthreads();
        for (int j = tid; j < 8192; j += 256) {
            int m = j >> 7, o = j & 127;
            int mn = (MODES - m) & 63;
            float a = tile[m * 129 + o];
            float bb = tile[mn * 129 + o];
            size_t d = (size_t)m * 16384 + (size_t)i * 128 + o;
            g_We[d] = 0.5f * (a + bb);
            g_Wo[d] = 0.5f * (a - bb);
        }
    } else {
        int j = (b - 128) * 256 + tid;   // 0..8191
        if (j < 2048) {
            float s, c;
            sincospif((float)j * (1.0f / 2048.0f), &s, &c);
            g_CAS[j] = c + s;
        } else if (j < 4096) {
            int idx = j - 2048;
            int k = idx >> 5, q = idx & 31;
            float w = 1.0f;
            #pragma unroll
            for (int t = 0; t < 5; t++) {
                if ((q >> t) & 1) {
                    float s, c;
                    sincospif((float)(k << t) * (1.0f / 2048.0f), &s, &c);
                    w *= (c + s);
                }
            }
            g_OM[idx] = w;
        }
    }
}

__device__ __forceinline__ int brev4(int r) {
    return ((r & 1) << 3) | ((r & 2) << 1) | ((r & 4) >> 1) | ((r & 8) >> 3);
}

// ---------------- forward (R12, unchanged) ----------------
__global__ __launch_bounds__(256, 6) void forward_kernel(const float* __restrict__ x) {
    __shared__ float buf[4096];
    __shared__ float cas32s[64];
    int h = threadIdx.x, row = blockIdx.x;
    int lane = h & 31, wrp = h >> 5;

    if (h < 64) cas32s[h] = g_CAS[h << 5];

    const float* xr = x + (size_t)row * NN;
    float v[16];
    #pragma unroll
    for (int r = 0; r < 16; r++) v[r] = xr[h + (r << 8)];

    float om[8];
    #pragma unroll
    for (int c = 0; c < 8; c++) om[c] = g_OM[((wrp + (c << 3)) << 5) + lane];

    #pragma unroll
    for (int r = 0; r < 8; r++) { float a = v[r], b = v[r + 8]; v[r] = a + b; v[r + 8] = a - b; }
    #pragma unroll
    for (int r = 0; r < 16; r++) if (!(r & 4)) { float a = v[r], b = v[r + 4]; v[r] = a + b; v[r + 4] = a - b; }
    {
        const float TW9[4] = {1.f, SQ2, 1.f, 0.f};
        #pragma unroll
        for (int r = 0; r < 16; r++) if (!(r & 2)) {
            int kt = ((r >> 3) & 1) | (((r >> 2) & 1) << 1);
            float w = TW9[kt], a = v[r], b = v[r + 2];
            v[r] = fmaf(w, b, a); v[r + 2] = fmaf(-w, b, a);
        }
    }
    {
        const float TW8[8] = {1.f, C256, SQ2, C256, 1.f, C1280, 0.f, -C1280};
        #pragma unroll
        for (int r = 0; r < 16; r += 2) {
            int kt = ((r >> 3) & 1) | (((r >> 2) & 1) << 1) | (((r >> 1) & 1) << 2);
            float w = TW8[kt], a = v[r], b = v[r + 1];
            v[r] = fmaf(w, b, a); v[r + 1] = fmaf(-w, b, a);
        }
    }
    #pragma unroll
    for (int r = 0; r < 16; r++) buf[h + (brev4(r) << 8)] = v[r];
    __syncthreads();

    int hi3 = wrp;
    int base = (h & 31) + (hi3 << 8);
    float u[16];
    #pragma unroll
    for (int r = 0; r < 16; r++) u[r] = buf[base + ((r & 7) << 5) + ((r & 8) << 8)];
    #pragma unroll
    for (int r = 0; r < 16; r++) if (!(r & 4)) {
        float w = cas32s[(hi3 + (r & 8)) << 2];
        float a = u[r], b = u[r + 4];
        u[r] = fmaf(w, b, a); u[r + 4] = fmaf(-w, b, a);
    }
    #pragma unroll
    for (int r = 0; r < 16; r++) if (!(r & 2)) {
        float w = cas32s[(hi3 + (r & 8) + ((r & 4) << 2)) << 1];
        float a = u[r], b = u[r + 2];
        u[r] = fmaf(w, b, a); u[r + 2] = fmaf(-w, b, a);
    }
    #pragma unroll
    for (int r = 0; r < 16; r += 2) {
        float w = cas32s[hi3 + (r & 8) + ((r & 4) << 2) + ((r & 2) << 4)];
        u[r] = fmaf(w, u[r + 1], u[r]);
    }

    float val[8];
    #pragma unroll
    for (int c = 0; c < 8; c++) {
        int j = ((c & 1) << 2) | (c & 2) | ((c & 4) >> 2);
        val[c] = om[c] * u[2 * j];
    }
    bool b4 = (lane & 16) != 0, b3 = (lane & 8) != 0, b2 = (lane & 4) != 0;
    float a4[4];
    #pragma unroll
    for (int c = 0; c < 4; c++) {
        float keep = b4 ? val[c + 4] : val[c];
        float give = b4 ? val[c] : val[c + 4];
        a4[c] = keep + __shfl_xor_sync(0xffffffffu, give, 16);
    }
    float a2[2];
    #pragma unroll
    for (int c = 0; c < 2; c++) {
        float keep = b3 ? a4[c + 2] : a4[c];
        float give = b3 ? a4[c] : a4[c + 2];
        a2[c] = keep + __shfl_xor_sync(0xffffffffu, give, 8);
    }
    float e;
    {
        float keep = b2 ? a2[1] : a2[0];
        float give = b2 ? a2[0] : a2[1];
        e = keep + __shfl_xor_sync(0xffffffffu, give, 4);
    }
    e += __shfl_xor_sync(0xffffffffu, e, 2);
    e += __shfl_xor_sync(0xffffffffu, e, 1);
    if ((lane & 3) == 0) g_Y[(wrp + ((lane >> 2) << 3)) * ROWS + row] = e;
}

// ---------------- mix (R12, unchanged) ----------------
__device__ __forceinline__ void cp16(uint32_t daddr, const void* gptr) {
    asm volatile("cp.async.cg.shared.global [%0], [%1], 16;" :: "r"(daddr), "l"(gptr));
}

__global__ __launch_bounds__(128) void mix_kernel() {
    __shared__ float Ys[8 * CH];
    __shared__ float Yn[8 * CH];
    extern __shared__ float4 Wbuf[];

    int m = blockIdx.x >> 3, g = blockIdx.x & 7;
    int mn = (MODES - m) & 63;
    int tid = threadIdx.x;
    int oq = tid & 31, bg = tid >> 5;

    const float* We = g_We + (size_t)m * 16384;
    const float* Wo = g_Wo + (size_t)m * 16384;
    uint32_t wb = (uint32_t)__cvta_generic_to_shared(Wbuf);

    #define ISSUE_CHUNK(c, s) do {                                              \
        const float4* se = (const float4*)(We + (c) * 2048);                    \
        const float4* so = (const float4*)(Wo + (c) * 2048);                    \
        uint32_t de = wb + (uint32_t)((s) * 2 + 0) * 8192;                      \
        uint32_t dn = wb + (uint32_t)((s) * 2 + 1) * 8192;                      \
        _Pragma("unroll")                                                       \
        for (int jj = 0; jj < 4; jj++) {                                        \
            int idx = tid + jj * 128;                                           \
            cp16(de + idx * 16, se + idx);                                      \
            cp16(dn + idx * 16, so + idx);                                      \
        }                                                                       \
        asm volatile("cp.async.commit_group;" ::: "memory");                    \
    } while (0)

    ISSUE_CHUNK(0, 0);
    ISSUE_CHUNK(1, 1);

    for (int idx = tid; idx < 1024; idx += 128) {
        Ys[idx] = g_Y[m * ROWS + g * 1024 + idx];
        Yn[idx] = g_Y[mn * ROWS + g * 1024 + idx];
    }

    float4 a0 = {0,0,0,0}, a1 = {0,0,0,0};
    int l0 = 2 * bg, l1 = l0 + 1;

    #pragma unroll 1
    for (int c = 0; c < 8; c++) {
        if (c < 7) asm volatile("cp.async.wait_group 1;" ::: "memory");
        else       asm volatile("cp.async.wait_group 0;" ::: "memory");
        __syncthreads();

        const float4* Wef = &Wbuf[(size_t)((c & 1) * 2 + 0) * 512];
        const float4* Wof = &Wbuf[(size_t)((c & 1) * 2 + 1) * 512];
        #pragma unroll
        for (int ii = 0; ii < 16; ii++) {
            float4 we = Wef[ii * 32 + oq];
            float4 wo = Wof[ii * 32 + oq];
            int i = c * 16 + ii;
            float y0 = Ys[l0 * CH + i], z0 = Yn[l0 * CH + i];
            float y1 = Ys[l1 * CH + i], z1 = Yn[l1 * CH + i];
            a0.x = fmaf(y0, we.x, a0.x); a0.x = fmaf(z0, wo.x, a0.x);
            a0.y = fmaf(y0, we.y, a0.y); a0.y = fmaf(z0, wo.y, a0.y);
            a0.z = fmaf(y0, we.z, a0.z); a0.z = fmaf(z0, wo.z, a0.z);
            a0.w = fmaf(y0, we.w, a0.w); a0.w = fmaf(z0, wo.w, a0.w);
            a1.x = fmaf(y1, we.x, a1.x); a1.x = fmaf(z1, wo.x, a1.x);
            a1.y = fmaf(y1, we.y, a1.y); a1.y = fmaf(z1, wo.y, a1.y);
            a1.z = fmaf(y1, we.z, a1.z); a1.z = fmaf(z1, wo.z, a1.z);
            a1.w = fmaf(y1, we.w, a1.w); a1.w = fmaf(z1, wo.w, a1.w);
        }
        __syncthreads();
        if (c < 6) ISSUE_CHUNK(c + 2, c & 1);
    }

    const float inv = 1.0f / 4096.0f;
    float4* Z4 = (float4*)g_Z;
    float4 s0 = make_float4(a0.x * inv, a0.y * inv, a0.z * inv, a0.w * inv);
    float4 s1 = make_float4(a1.x * inv, a1.y * inv, a1.z * inv, a1.w * inv);
    int b0 = g * 8 + l0;
    Z4[(size_t)m * 2048 + (size_t)b0 * 32 + oq]       = s0;
    Z4[(size_t)m * 2048 + (size_t)(b0 + 1) * 32 + oq] = s1;
    #undef ISSUE_CHUNK
}

// ---------------- inverse (R12 structure; float4 cas load, stcs stores) ----------------
__global__ __launch_bounds__(256, 6) void inverse_kernel(float* __restrict__ out) {
    __shared__ float buf[4096];
    __shared__ __align__(16) float cas_s[2048];
    __shared__ float zb[64];
    int h = threadIdx.x, row = blockIdx.x;

    {
        float4* c4 = (float4*)cas_s;
        const float4* s4 = (const float4*)g_CAS;
        c4[h] = s4[h];
        c4[h + 256] = s4[h + 256];
    }
    if (h < 64) zb[h] = g_Z[(size_t)h * ROWS + row];   // [m][row] layout
    __syncthreads();

    float v[16];
    #pragma unroll
    for (int r = 0; r < 16; r++) v[r] = zb[(h & 7) + ((r & 7) << 3)];

    int hk = (h >> 3) & 31;
    #pragma unroll
    for (int r = 0; r < 16; r++) if (!(r & 4)) {
        float w = cas_s[(hk + ((r & 8) << 2)) << 5];
        float a = v[r], b = v[r + 4];
        v[r] = fmaf(w, b, a); v[r + 4] = fmaf(-w, b, a);
    }
    #pragma unroll
    for (int r = 0; r < 16; r++) if (!(r & 2)) {
        float w = cas_s[(hk + ((r & 8) << 2) + ((r & 4) << 4)) << 4];
        float a = v[r], b = v[r + 2];
        v[r] = fmaf(w, b, a); v[r + 2] = fmaf(-w, b, a);
    }
    #pragma unroll
    for (int r = 0; r < 16; r += 2) {
        float w = cas_s[(hk + ((r & 8) << 2) + ((r & 4) << 4) + ((r & 2) << 6)) << 3];
        float a = v[r], b = v[r + 1];
        v[r] = fmaf(w, b, a); v[r + 1] = fmaf(-w, b, a);
    }

    #pragma unroll
    for (int r = 0; r < 16; r++) {
        int a = h + (brev4(r) << 8);
        buf[a ^ ((a >> 5) & 7)] = v[r];
    }
    __syncthreads();
    #pragma unroll
    for (int r = 0; r < 16; r++) {
        int a = (r & 7) + (h << 3) + ((r & 8) << 8);
        v[r] = buf[a ^ ((a >> 5) & 7)];
    }

    #pragma unroll
    for (int r = 0; r < 16; r++) if (!(r & 4)) {
        float w = cas_s[(h + ((r & 8) << 5)) << 2];
        float a = v[r], b = v[r + 4];
        v[r] = fmaf(w, b, a); v[r + 4] = fmaf(-w, b, a);
    }
    #pragma unroll
    for (int r = 0; r < 16; r++) if (!(r & 2)) {
        float w = cas_s[(h + ((r & 8) << 5) + ((r & 4) << 7)) << 1];
        float a = v[r], b = v[r + 2];
        v[r] = fmaf(w, b, a); v[r + 2] = fmaf(-w, b, a);
    }
    #pragma unroll
    for (int r = 0; r < 16; r += 2) {
        float w = cas_s[h + ((r & 8) << 5) + ((r & 4) << 7) + ((r & 2) << 9)];
        float a = v[r], b = v[r + 1];
        v[r] = fmaf(w, b, a); v[r + 1] = fmaf(-w, b, a);
    }

    // direct coalesced streaming stores (output never re-read)
    float* orow = out + (size_t)row * NN;
    #pragma unroll
    for (int r = 0; r < 16; r++) __stcs(&orow[h + (brev4(r) << 8)], v[r]);
}

extern "C" void kernel_launch(void* const* d_in, const int* in_sizes, int n_in,
                              void* d_out, int out_size) {
    const float* x  = (const float*)d_in[0];
    const float* w1 = (const float*)d_in[1];
    float* out = (float*)d_out;

    build_all_kernel<<<160, 256>>>(w1);          // launch 0
    forward_kernel<<<ROWS, 256>>>(x);            // launch 1
    mix_kernel<<<MODES * 8, 128, 32768>>>();     // launch 2
    inverse_kernel<<<ROWS, 256>>>(out);          // launch 3  <- ncu target
}